// round 2
// baseline (speedup 1.0000x reference)
#include <cuda_runtime.h>
#include <cstdint>

#define LQv 2048
#define BZv 8
#define Dv 1024
#define NHv 16
#define NKv 4
#define FFv 2048
#define HDv 64
#define MROWS (LQv * BZv)   // 16384

// ---------------- scratch (no allocations allowed) ----------------
// One blob; offsets in floats.
#define OFF_Q    ((size_t)0)
#define OFF_VAL  (OFF_Q    + (size_t)MROWS * Dv)
#define OFF_OFF  (OFF_VAL  + (size_t)MROWS * Dv)
#define OFF_ATT  (OFF_OFF  + (size_t)MROWS * NHv * NKv)
#define OFF_AO   (OFF_ATT  + (size_t)MROWS * NHv * NKv)
#define OFF_X    (OFF_AO   + (size_t)MROWS * Dv)
#define OFF_Y    (OFF_X    + (size_t)MROWS * Dv)
#define OFF_H    (OFF_Y    + (size_t)MROWS * Dv)
#define SCRATCH_FLOATS (OFF_H + (size_t)MROWS * FFv)

__device__ float g_scratch[SCRATCH_FLOATS];

// ---------------- elementwise add: q = src + pos ----------------
__global__ __launch_bounds__(256)
void add_k(const float* __restrict__ a, const float* __restrict__ b,
           float* __restrict__ o)
{
    size_t i = ((size_t)blockIdx.x * 256 + threadIdx.x) * 4;
    float4 va = *reinterpret_cast<const float4*>(a + i);
    float4 vb = *reinterpret_cast<const float4*>(b + i);
    float4 vo;
    vo.x = va.x + vb.x; vo.y = va.y + vb.y;
    vo.z = va.z + vb.z; vo.w = va.w + vb.w;
    *reinterpret_cast<float4*>(o + i) = vo;
}

// ---------------- generic tiled fp32 GEMM ----------------
// C[M,N] = A[M,K] @ B[K,N] + bias, row-major. BM=BN=128, BK=16, 256 thr, 8x8/thr.
enum { EPI_BIAS = 0, EPI_MASK = 1, EPI_RELU = 2, EPI_RES = 3 };

template <int EPI>
__global__ __launch_bounds__(256)
void gemm_k(const float* __restrict__ A, const float* __restrict__ B,
            const float* __restrict__ bias, const float* __restrict__ res,
            const unsigned char* __restrict__ mask,
            int M, int N, int K, float* __restrict__ C)
{
    __shared__ float As[16][128];
    __shared__ float Bs[16][128];

    const int tid = threadIdx.x;
    const int ty = tid >> 4;       // 0..15  (row group)
    const int tx = tid & 15;       // 0..15  (col group)
    const int row0 = blockIdx.y * 128;
    const int col0 = blockIdx.x * 128;

    float acc[8][8];
#pragma unroll
    for (int i = 0; i < 8; i++)
#pragma unroll
        for (int j = 0; j < 8; j++) acc[i][j] = 0.f;

    for (int k0 = 0; k0 < K; k0 += 16) {
        // --- load A tile (128x16), store transposed As[k][row] ---
#pragma unroll
        for (int it = 0; it < 2; it++) {
            int pos = tid + it * 256;          // 0..511
            int ar = pos >> 2;                 // 0..127
            int ac = (pos & 3) << 2;           // 0,4,8,12
            float4 v = *reinterpret_cast<const float4*>(
                &A[(size_t)(row0 + ar) * K + k0 + ac]);
            As[ac + 0][ar] = v.x;
            As[ac + 1][ar] = v.y;
            As[ac + 2][ar] = v.z;
            As[ac + 3][ar] = v.w;
        }
        // --- load B tile (16x128) ---
#pragma unroll
        for (int it = 0; it < 2; it++) {
            int pos = tid + it * 256;
            int br = pos >> 5;                 // 0..15
            int bc = (pos & 31) << 2;          // 0..124
            float4 v = make_float4(0.f, 0.f, 0.f, 0.f);
            if (col0 + bc < N)
                v = *reinterpret_cast<const float4*>(
                    &B[(size_t)(k0 + br) * N + col0 + bc]);
            *reinterpret_cast<float4*>(&Bs[br][bc]) = v;
        }
        __syncthreads();

#pragma unroll
        for (int kk = 0; kk < 16; kk++) {
            float a[8], b[8];
            *reinterpret_cast<float4*>(&a[0]) =
                *reinterpret_cast<const float4*>(&As[kk][ty * 8 + 0]);
            *reinterpret_cast<float4*>(&a[4]) =
                *reinterpret_cast<const float4*>(&As[kk][ty * 8 + 4]);
            *reinterpret_cast<float4*>(&b[0]) =
                *reinterpret_cast<const float4*>(&Bs[kk][tx * 8 + 0]);
            *reinterpret_cast<float4*>(&b[4]) =
                *reinterpret_cast<const float4*>(&Bs[kk][tx * 8 + 4]);
#pragma unroll
            for (int i = 0; i < 8; i++)
#pragma unroll
                for (int j = 0; j < 8; j++)
                    acc[i][j] += a[i] * b[j];
        }
        __syncthreads();
    }

    // --- epilogue ---
#pragma unroll
    for (int i = 0; i < 8; i++) {
        int r = row0 + ty * 8 + i;
        unsigned char mrow = 0;
        if (EPI == EPI_MASK) {
            int b = r & (BZv - 1);
            int q = r >> 3;
            mrow = mask[b * LQv + q];
        }
#pragma unroll
        for (int j = 0; j < 8; j++) {
            int c = col0 + tx * 8 + j;
            if (c < N) {
                float v = acc[i][j] + bias[c];
                if (EPI == EPI_MASK && mrow) v = 0.f;
                if (EPI == EPI_RELU) v = fmaxf(v, 0.f);
                if (EPI == EPI_RES) v += res[(size_t)r * N + c];
                C[(size_t)r * N + c] = v;
            }
        }
    }
}

// ---------------- softmax + grid_sample1d + head combine ----------------
// One thread per (q, b, h, c); 64 threads share a (q,b,h) group.
__global__ __launch_bounds__(256)
void sample_k(const float* __restrict__ value,   // [Lv, BZ, D]
              const float* __restrict__ offraw,  // [MROWS, 64] (h*4+k)
              const float* __restrict__ attnraw, // [MROWS, 64]
              const float* __restrict__ refp,    // [BZ, LQ]
              const float* __restrict__ snip,    // [BZ]
              float* __restrict__ out)           // [MROWS, D]
{
    int t = blockIdx.x * 256 + threadIdx.x;
    int c = t & 63;
    int gidx = t >> 6;          // ((q*BZ + b)*NH + h)
    int h = gidx & (NHv - 1);
    int rb = gidx >> 4;         // q*BZ + b
    int b = rb & (BZv - 1);
    int q = rb >> 3;

    const float* al = attnraw + (size_t)rb * (NHv * NKv) + h * NKv;
    const float* ol = offraw  + (size_t)rb * (NHv * NKv) + h * NKv;

    float a0 = al[0], a1 = al[1], a2 = al[2], a3 = al[3];
    float m = fmaxf(fmaxf(a0, a1), fmaxf(a2, a3));
    float e0 = __expf(a0 - m), e1 = __expf(a1 - m);
    float e2 = __expf(a2 - m), e3 = __expf(a3 - m);
    float inv_s = 1.f / (e0 + e1 + e2 + e3);
    float ak[4] = {e0 * inv_s, e1 * inv_s, e2 * inv_s, e3 * inv_s};

    float refv = refp[b * LQv + q];
    float inv_sn = 1.f / snip[b];

    float acc = 0.f;
#pragma unroll
    for (int k = 0; k < NKv; k++) {
        float loc = refv + ol[k] * inv_sn;
        float x = loc * (float)(LQv - 1);        // align_corners sample coord
        float x0f = floorf(x);
        float w1 = x - x0f;
        float w0 = 1.f - w1;
        // safe cast (clamp range before int conversion)
        float x0c = fminf(fmaxf(x0f, -2.f), (float)(LQv + 1));
        int i0 = (int)x0c;
        int i1 = i0 + 1;
        float v0 = 0.f, v1 = 0.f;
        if (x0f >= 0.f && x0f <= (float)(LQv - 1))
            v0 = value[((size_t)i0 * BZv + b) * Dv + h * HDv + c];
        if (x0f >= -1.f && x0f <= (float)(LQv - 2))
            v1 = value[((size_t)i1 * BZv + b) * Dv + h * HDv + c];
        acc += ak[k] * (w0 * v0 + w1 * v1);
    }
    out[(size_t)rb * Dv + h * HDv + c] = acc;
}

// ---------------- LayerNorm over D=1024, one block per row ----------------
__global__ __launch_bounds__(256)
void ln_k(const float* __restrict__ in, const float* __restrict__ gam,
          const float* __restrict__ bet, float* __restrict__ out)
{
    int row = blockIdx.x;
    const float* xp = in + (size_t)row * Dv;
    int c4 = threadIdx.x * 4;
    float4 v = *reinterpret_cast<const float4*>(&xp[c4]);
    float s  = v.x + v.y + v.z + v.w;
    float ss = v.x * v.x + v.y * v.y + v.z * v.z + v.w * v.w;
#pragma unroll
    for (int o = 16; o > 0; o >>= 1) {
        s  += __shfl_xor_sync(0xffffffffu, s, o);
        ss += __shfl_xor_sync(0xffffffffu, ss, o);
    }
    __shared__ float sh_s[8], sh_ss[8];
    int w = threadIdx.x >> 5;
    if ((threadIdx.x & 31) == 0) { sh_s[w] = s; sh_ss[w] = ss; }
    __syncthreads();
    s = 0.f; ss = 0.f;
#pragma unroll
    for (int i = 0; i < 8; i++) { s += sh_s[i]; ss += sh_ss[i]; }
    float mean = s * (1.f / Dv);
    float var  = ss * (1.f / Dv) - mean * mean;
    float inv  = rsqrtf(var + 1e-5f);
    float4 gv = *reinterpret_cast<const float4*>(&gam[c4]);
    float4 bv = *reinterpret_cast<const float4*>(&bet[c4]);
    float4 o;
    o.x = (v.x - mean) * inv * gv.x + bv.x;
    o.y = (v.y - mean) * inv * gv.y + bv.y;
    o.z = (v.z - mean) * inv * gv.z + bv.z;
    o.w = (v.w - mean) * inv * gv.w + bv.w;
    *reinterpret_cast<float4*>(&out[(size_t)row * Dv + c4]) = o;
}

// ---------------- launch ----------------
extern "C" void kernel_launch(void* const* d_in, const int* in_sizes, int n_in,
                              void* d_out, int out_size)
{
    const float* src  = (const float*)d_in[0];
    const float* pos  = (const float*)d_in[1];
    const unsigned char* mask = (const unsigned char*)d_in[2];
    const float* refp = (const float*)d_in[3];
    const float* snip = (const float*)d_in[4];
    const float* Wv   = (const float*)d_in[5];
    const float* bv   = (const float*)d_in[6];
    const float* Woff = (const float*)d_in[7];
    const float* boff = (const float*)d_in[8];
    const float* Wa   = (const float*)d_in[9];
    const float* ba   = (const float*)d_in[10];
    const float* Wo   = (const float*)d_in[11];
    const float* bo   = (const float*)d_in[12];
    const float* W1   = (const float*)d_in[13];
    const float* b1   = (const float*)d_in[14];
    const float* W2   = (const float*)d_in[15];
    const float* b2   = (const float*)d_in[16];
    const float* g1   = (const float*)d_in[17];
    const float* be1  = (const float*)d_in[18];
    const float* g2   = (const float*)d_in[19];
    const float* be2  = (const float*)d_in[20];
    float* outp = (float*)d_out;

    float* scratch = nullptr;
    cudaGetSymbolAddress((void**)&scratch, g_scratch);
    float* q    = scratch + OFF_Q;
    float* val  = scratch + OFF_VAL;
    float* off  = scratch + OFF_OFF;
    float* attn = scratch + OFF_ATT;
    float* ao   = scratch + OFF_AO;
    float* x    = scratch + OFF_X;
    float* y    = scratch + OFF_Y;
    float* hh   = scratch + OFF_H;

    const dim3 blk(256);
    const dim3 gD(Dv / 128, MROWS / 128);     // N=1024
    const dim3 gS(1, MROWS / 128);            // N=64
    const dim3 gF(FFv / 128, MROWS / 128);    // N=2048

    // q = src + pos
    add_k<<<(size_t)MROWS * Dv / 4 / 256, blk>>>(src, pos, q);

    // value = src @ Wv + bv, masked
    gemm_k<EPI_MASK><<<gD, blk>>>(src, Wv, bv, nullptr, mask,
                                  MROWS, Dv, Dv, val);
    // offsets / attn logits
    gemm_k<EPI_BIAS><<<gS, blk>>>(q, Woff, boff, nullptr, nullptr,
                                  MROWS, NHv * NKv, Dv, off);
    gemm_k<EPI_BIAS><<<gS, blk>>>(q, Wa, ba, nullptr, nullptr,
                                  MROWS, NHv * NKv, Dv, attn);

    // softmax + grid-sample + combine -> attn_out
    sample_k<<<(size_t)MROWS * NHv * HDv / 256, blk>>>(val, off, attn,
                                                       refp, snip, ao);

    // out proj + residual, then LN1
    gemm_k<EPI_RES><<<gD, blk>>>(ao, Wo, bo, src, nullptr,
                                 MROWS, Dv, Dv, y);
    ln_k<<<MROWS, blk>>>(y, g1, be1, x);

    // FFN
    gemm_k<EPI_RELU><<<gF, blk>>>(x, W1, b1, nullptr, nullptr,
                                  MROWS, FFv, Dv, hh);
    gemm_k<EPI_RES><<<gD, blk>>>(hh, W2, b2, x, nullptr,
                                 MROWS, Dv, FFv, y);
    ln_k<<<MROWS, blk>>>(y, g2, be2, outp);
}

// round 4
// speedup vs baseline: 1.1605x; 1.1605x over previous
#include <cuda_runtime.h>
#include <cstdint>

#define LQv 2048
#define BZv 8
#define Dv 1024
#define NHv 16
#define NKv 4
#define FFv 2048
#define HDv 64
#define MROWS (LQv * BZv)   // 16384

// ================= scratch (single blob, no allocations) =================
#define MDsz ((size_t)MROWS * Dv)
#define OFF_Q     ((size_t)0)
#define OFF_VAL   (OFF_Q   + MDsz)
#define OFF_OFFA  (OFF_VAL + MDsz)                       // [MROWS,128]
#define OFF_AO    (OFF_OFFA + (size_t)MROWS * 128)
#define OFF_X     (OFF_AO  + MDsz)
#define OFF_Y     (OFF_X   + MDsz)
#define OFF_H     (OFF_Y   + MDsz)                       // [MROWS,FF]
#define OFF_WOFA  (OFF_H   + (size_t)MROWS * FFv)        // [1024,128] row-major
#define OFF_BOFA  (OFF_WOFA + (size_t)Dv * 128)          // [128]
#define SCRATCH_FLOATS (OFF_BOFA + 128)

__device__ float g_scratch[SCRATCH_FLOATS];

__device__ __forceinline__ uint32_t to_tf32_bits(float x) {
    uint32_t u;
    asm("cvt.rn.tf32.f32 %0, %1;" : "=r"(u) : "f"(x));
    return u;
}

// ================= prep: fuse Woff|Wa -> Wofa[K=1024][N=128] =================
__global__ __launch_bounds__(256)
void prep_offa_k(const float* __restrict__ Woff, const float* __restrict__ boff,
                 const float* __restrict__ Wa,   const float* __restrict__ ba,
                 float* __restrict__ Wofa, float* __restrict__ bout)
{
    int idx = blockIdx.x * 256 + threadIdx.x;   // 1024*128
    int k = idx >> 7, n = idx & 127;
    float v = (n < 64) ? Woff[(size_t)k * 64 + n] : Wa[(size_t)k * 64 + (n - 64)];
    Wofa[idx] = v;
    if (idx < 128) bout[idx] = (idx < 64) ? boff[idx] : ba[idx - 64];
}

// ================= elementwise add =================
__global__ __launch_bounds__(256)
void add_k(const float* __restrict__ a, const float* __restrict__ b,
           float* __restrict__ o)
{
    size_t i = ((size_t)blockIdx.x * 256 + threadIdx.x) * 4;
    float4 va = *reinterpret_cast<const float4*>(a + i);
    float4 vb = *reinterpret_cast<const float4*>(b + i);
    float4 vo;
    vo.x = va.x + vb.x; vo.y = va.y + vb.y;
    vo.z = va.z + vb.z; vo.w = va.w + vb.w;
    *reinterpret_cast<float4*>(o + i) = vo;
}

// ================= tf32 mma.sync GEMM =================
// C[M,N] = A[M,K] @ B[K,N] + bias (+epi). BM=BN=128, BK=32, 256 thr, 8 warps.
// SMEM holds fragment-ordered tiles:
//  A: per kk(4) per mt(8): 32 lanes x 4 floats  -> As[kk*1024 + mt*128 + lane*4 + p]
//  B: per kk(4) per nt(16): 32 lanes x 2 floats -> Bs[kk*1024 + nt*64 + lane*2 + b]
enum { EPI_BIAS = 0, EPI_MASK = 1, EPI_RELU = 2, EPI_RES = 3 };

#define GSMEM_FLOATS (4 * 4096)           // 2 bufs x (A 4096 + B 4096)
#define GSMEM_BYTES  (GSMEM_FLOATS * 4)   // 64 KB

__device__ __forceinline__ void mma_tf32(float* c, const uint32_t* a,
                                         const uint32_t* b)
{
    asm volatile(
        "mma.sync.aligned.m16n8k8.row.col.f32.tf32.tf32.f32 "
        "{%0,%1,%2,%3}, {%4,%5,%6,%7}, {%8,%9}, {%0,%1,%2,%3};"
        : "+f"(c[0]), "+f"(c[1]), "+f"(c[2]), "+f"(c[3])
        : "r"(a[0]), "r"(a[1]), "r"(a[2]), "r"(a[3]),
          "r"(b[0]), "r"(b[1]));
}

template <int EPI>
__global__ __launch_bounds__(256)
void mma_gemm(const float* __restrict__ A, const float* __restrict__ B,
              const float* __restrict__ bias, const float* __restrict__ res,
              const unsigned char* __restrict__ mask,
              int K, int N, float* __restrict__ C)
{
    extern __shared__ float sm[];
    float* As = sm;            // 2 x 4096
    float* Bs = sm + 8192;     // 2 x 4096

    const int tid = threadIdx.x;
    const int lane = tid & 31;
    const int wid = tid >> 5;
    const int warp_m = wid & 1;        // 2 warps in M (64 rows each)
    const int warp_n = wid >> 1;       // 4 warps in N (32 cols each)
    const int row0 = blockIdx.y * 128;
    const int col0 = blockIdx.x * 128;

    float acc[4][4][4];
#pragma unroll
    for (int mi = 0; mi < 4; mi++)
#pragma unroll
        for (int ni = 0; ni < 4; ni++)
#pragma unroll
            for (int j = 0; j < 4; j++) acc[mi][ni][j] = 0.f;

    const int NC = K >> 5;
    float4 av[4], bv[4];

    // ---- staging lambda-equivalents (macros via code dup) ----
#define LDG_TILES(c_)                                                        \
    {                                                                        \
        const int kbase = (c_) << 5;                                         \
        _Pragma("unroll")                                                    \
        for (int it = 0; it < 4; it++) {                                     \
            int lin = tid + it * 256;          /* A: 0..1023 */              \
            int m = lin >> 3, kc4 = lin & 7;                                 \
            av[it] = *reinterpret_cast<const float4*>(                       \
                &A[(size_t)(row0 + m) * K + kbase + kc4 * 4]);               \
        }                                                                    \
        _Pragma("unroll")                                                    \
        for (int it = 0; it < 4; it++) {                                     \
            int lin = tid + it * 256;          /* B: 0..1023 */              \
            int k = lin >> 5, nc4 = lin & 31;                                \
            bv[it] = *reinterpret_cast<const float4*>(                       \
                &B[(size_t)(kbase + k) * N + col0 + nc4 * 4]);               \
        }                                                                    \
    }

#define STS_TILES(buf_)                                                      \
    {                                                                        \
        float* as = As + (buf_) * 4096;                                      \
        float* bs = Bs + (buf_) * 4096;                                      \
        _Pragma("unroll")                                                    \
        for (int it = 0; it < 4; it++) {                                     \
            int lin = tid + it * 256;                                        \
            int m = lin >> 3, kc4 = lin & 7;                                 \
            int g = m & 7, p_lo = (m >> 3) & 1, mt = m >> 4;                 \
            int kk = kc4 >> 1, p_hi = kc4 & 1;                               \
            int base = kk * 1024 + mt * 128 + g * 16 + p_lo + 2 * p_hi;      \
            const float* f = reinterpret_cast<const float*>(&av[it]);        \
            _Pragma("unroll")                                                \
            for (int j = 0; j < 4; j++)                                      \
                as[base + j * 4] =                                           \
                    __uint_as_float(to_tf32_bits(f[j]));                     \
        }                                                                    \
        _Pragma("unroll")                                                    \
        for (int it = 0; it < 4; it++) {                                     \
            int lin = tid + it * 256;                                        \
            int k = lin >> 5, nc4 = lin & 31;                                \
            int kk = k >> 3, kloc = k & 7;                                   \
            int t = kloc & 3, bx = kloc >> 2;                                \
            const float* f = reinterpret_cast<const float*>(&bv[it]);        \
            _Pragma("unroll")                                                \
            for (int j = 0; j < 4; j++) {                                    \
                int n = nc4 * 4 + j;                                         \
                int nt = n >> 3, g = n & 7;                                  \
                bs[kk * 1024 + nt * 64 + (g * 4 + t) * 2 + bx] =             \
                    __uint_as_float(to_tf32_bits(f[j]));                     \
            }                                                                \
        }                                                                    \
    }

    LDG_TILES(0);
    STS_TILES(0);
    __syncthreads();

    for (int c = 0; c < NC; c++) {
        const int buf = c & 1;
        if (c + 1 < NC) LDG_TILES(c + 1);

        const float* as = As + buf * 4096;
        const float* bs = Bs + buf * 4096;
#pragma unroll
        for (int kk = 0; kk < 4; kk++) {
            uint32_t af[4][4];
            uint32_t bf[4][2];
#pragma unroll
            for (int mi = 0; mi < 4; mi++) {
                uint4 v = *reinterpret_cast<const uint4*>(
                    &as[kk * 1024 + (warp_m * 4 + mi) * 128 + lane * 4]);
                af[mi][0] = v.x; af[mi][1] = v.y;
                af[mi][2] = v.z; af[mi][3] = v.w;
            }
#pragma unroll
            for (int ni = 0; ni < 4; ni++) {
                uint2 v = *reinterpret_cast<const uint2*>(
                    &bs[kk * 1024 + (warp_n * 4 + ni) * 64 + lane * 2]);
                bf[ni][0] = v.x; bf[ni][1] = v.y;
            }
#pragma unroll
            for (int mi = 0; mi < 4; mi++)
#pragma unroll
                for (int ni = 0; ni < 4; ni++)
                    mma_tf32(acc[mi][ni], af[mi], bf[ni]);
        }

        if (c + 1 < NC) {
            STS_TILES(buf ^ 1);
            __syncthreads();
        }
    }

    // ---- epilogue ----
    const int g = lane >> 2, t = lane & 3;
#pragma unroll
    for (int mi = 0; mi < 4; mi++) {
        int rA = row0 + warp_m * 64 + mi * 16 + g;     // rows rA, rA+8
#pragma unroll
        for (int half = 0; half < 2; half++) {
            int r = rA + half * 8;
            unsigned char mrow = 0;
            if (EPI == EPI_MASK) {
                int b = r & (BZv - 1);
                int qq = r >> 3;
                mrow = mask[b * LQv + qq];
            }
#pragma unroll
            for (int ni = 0; ni < 4; ni++) {
                int cc = col0 + warp_n * 32 + ni * 8 + t * 2;
                float v0 = acc[mi][ni][half * 2 + 0] + bias[cc + 0];
                float v1 = acc[mi][ni][half * 2 + 1] + bias[cc + 1];
                if (EPI == EPI_MASK && mrow) { v0 = 0.f; v1 = 0.f; }
                if (EPI == EPI_RELU) { v0 = fmaxf(v0, 0.f); v1 = fmaxf(v1, 0.f); }
                if (EPI == EPI_RES) {
                    float2 rv = *reinterpret_cast<const float2*>(
                        &res[(size_t)r * N + cc]);
                    v0 += rv.x; v1 += rv.y;
                }
                float2 o = make_float2(v0, v1);
                *reinterpret_cast<float2*>(&C[(size_t)r * N + cc]) = o;
            }
        }
    }
#undef LDG_TILES
#undef STS_TILES
}

// ================= softmax + grid_sample1d + head combine =================
// offa: [MROWS,128] — cols 0..63 offsets (h*4+k), 64..127 attn logits
__global__ __launch_bounds__(256)
void sample_k(const float* __restrict__ value,   // [Lv, BZ, D]
              const float* __restrict__ offa,    // [MROWS, 128]
              const float* __restrict__ refp,    // [BZ, LQ]
              const float* __restrict__ snip,    // [BZ]
              float* __restrict__ out)           // [MROWS, D]
{
    int t = blockIdx.x * 256 + threadIdx.x;
    int c = t & 63;
    int gidx = t >> 6;
    int h = gidx & (NHv - 1);
    int rb = gidx >> 4;
    int b = rb & (BZv - 1);
    int q = rb >> 3;

    const float* ol = offa + (size_t)rb * 128 + h * NKv;
    const float* al = ol + 64;

    float a0 = al[0], a1 = al[1], a2 = al[2], a3 = al[3];
    float m = fmaxf(fmaxf(a0, a1), fmaxf(a2, a3));
    float e0 = __expf(a0 - m), e1 = __expf(a1 - m);
    float e2 = __expf(a2 - m), e3 = __expf(a3 - m);
    float inv_s = 1.f / (e0 + e1 + e2 + e3);
    float ak[4] = {e0 * inv_s, e1 * inv_s, e2 * inv_s, e3 * inv_s};

    float refv = refp[b * LQv + q];
    float inv_sn = 1.f / snip[b];

    float acc = 0.f;
#pragma unroll
    for (int k = 0; k < NKv; k++) {
        float loc = refv + ol[k] * inv_sn;
        float x = loc * (float)(LQv - 1);
        float x0f = floorf(x);
        float w1 = x - x0f;
        float w0 = 1.f - w1;
        float x0c = fminf(fmaxf(x0f, -2.f), (float)(LQv + 1));
        int i0 = (int)x0c;
        int i1 = i0 + 1;
        float v0 = 0.f, v1 = 0.f;
        if (x0f >= 0.f && x0f <= (float)(LQv - 1))
            v0 = value[((size_t)i0 * BZv + b) * Dv + h * HDv + c];
        if (x0f >= -1.f && x0f <= (float)(LQv - 2))
            v1 = value[((size_t)i1 * BZv + b) * Dv + h * HDv + c];
        acc += ak[k] * (w0 * v0 + w1 * v1);
    }
    out[(size_t)rb * Dv + h * HDv + c] = acc;
}

// ================= LayerNorm D=1024 =================
__global__ __launch_bounds__(256)
void ln_k(const float* __restrict__ in, const float* __restrict__ gam,
          const float* __restrict__ bet, float* __restrict__ out)
{
    int row = blockIdx.x;
    const float* xp = in + (size_t)row * Dv;
    int c4 = threadIdx.x * 4;
    float4 v = *reinterpret_cast<const float4*>(&xp[c4]);
    float s  = v.x + v.y + v.z + v.w;
    float ss = v.x * v.x + v.y * v.y + v.z * v.z + v.w * v.w;
#pragma unroll
    for (int o = 16; o > 0; o >>= 1) {
        s  += __shfl_xor_sync(0xffffffffu, s, o);
        ss += __shfl_xor_sync(0xffffffffu, ss, o);
    }
    __shared__ float sh_s[8], sh_ss[8];
    int w = threadIdx.x >> 5;
    if ((threadIdx.x & 31) == 0) { sh_s[w] = s; sh_ss[w] = ss; }
    __syncthreads();
    s = 0.f; ss = 0.f;
#pragma unroll
    for (int i = 0; i < 8; i++) { s += sh_s[i]; ss += sh_ss[i]; }
    float mean = s * (1.f / Dv);
    float var  = ss * (1.f / Dv) - mean * mean;
    float inv  = rsqrtf(var + 1e-5f);
    float4 gv = *reinterpret_cast<const float4*>(&gam[c4]);
    float4 bvv = *reinterpret_cast<const float4*>(&bet[c4]);
    float4 o;
    o.x = (v.x - mean) * inv * gv.x + bvv.x;
    o.y = (v.y - mean) * inv * gv.y + bvv.y;
    o.z = (v.z - mean) * inv * gv.z + bvv.z;
    o.w = (v.w - mean) * inv * gv.w + bvv.w;
    *reinterpret_cast<float4*>(&out[(size_t)row * Dv + c4]) = o;
}

// ================= launch =================
extern "C" void kernel_launch(void* const* d_in, const int* in_sizes, int n_in,
                              void* d_out, int out_size)
{
    const float* src  = (const float*)d_in[0];
    const float* pos  = (const float*)d_in[1];
    const unsigned char* mask = (const unsigned char*)d_in[2];
    const float* refp = (const float*)d_in[3];
    const float* snip = (const float*)d_in[4];
    const float* Wv   = (const float*)d_in[5];
    const float* bv   = (const float*)d_in[6];
    const float* Woff = (const float*)d_in[7];
    const float* boff = (const float*)d_in[8];
    const float* Wa   = (const float*)d_in[9];
    const float* ba   = (const float*)d_in[10];
    const float* Wo   = (const float*)d_in[11];
    const float* bo   = (const float*)d_in[12];
    const float* W1   = (const float*)d_in[13];
    const float* b1   = (const float*)d_in[14];
    const float* W2   = (const float*)d_in[15];
    const float* b2   = (const float*)d_in[16];
    const float* g1   = (const float*)d_in[17];
    const float* be1  = (const float*)d_in[18];
    const float* g2   = (const float*)d_in[19];
    const float* be2  = (const float*)d_in[20];
    float* outp = (float*)d_out;

    float* scratch = nullptr;
    cudaGetSymbolAddress((void**)&scratch, g_scratch);
    float* q    = scratch + OFF_Q;
    float* val  = scratch + OFF_VAL;
    float* offa = scratch + OFF_OFFA;
    float* ao   = scratch + OFF_AO;
    float* x    = scratch + OFF_X;
    float* y    = scratch + OFF_Y;
    float* hh   = scratch + OFF_H;
    float* wofa = scratch + OFF_WOFA;
    float* bofa = scratch + OFF_BOFA;

    cudaFuncSetAttribute(mma_gemm<EPI_MASK>,
        cudaFuncAttributeMaxDynamicSharedMemorySize, GSMEM_BYTES);
    cudaFuncSetAttribute(mma_gemm<EPI_BIAS>,
        cudaFuncAttributeMaxDynamicSharedMemorySize, GSMEM_BYTES);
    cudaFuncSetAttribute(mma_gemm<EPI_RELU>,
        cudaFuncAttributeMaxDynamicSharedMemorySize, GSMEM_BYTES);
    cudaFuncSetAttribute(mma_gemm<EPI_RES>,
        cudaFuncAttributeMaxDynamicSharedMemorySize, GSMEM_BYTES);

    const dim3 blk(256);

    // prep (tiny)
    prep_offa_k<<<(Dv * 128) / 256, blk>>>(Woff, boff, Wa, ba, wofa, bofa);

    // q = src + pos
    add_k<<<(size_t)MROWS * Dv / 4 / 256, blk>>>(src, pos, q);

    // value = src @ Wv + bv (masked)
    mma_gemm<EPI_MASK><<<dim3(Dv / 128, MROWS / 128), blk, GSMEM_BYTES>>>(
        src, Wv, bv, nullptr, mask, Dv, Dv, val);

    // offsets + attn logits fused: [MROWS,128]
    mma_gemm<EPI_BIAS><<<dim3(1, MROWS / 128), blk, GSMEM_BYTES>>>(
        q, wofa, bofa, nullptr, nullptr, Dv, 128, offa);

    // softmax + grid-sample + combine
    sample_k<<<(size_t)MROWS * NHv * HDv / 256, blk>>>(val, offa, refp, snip, ao);

    // out proj + residual, LN1
    mma_gemm<EPI_RES><<<dim3(Dv / 128, MROWS / 128), blk, GSMEM_BYTES>>>(
        ao, Wo, bo, src, nullptr, Dv, Dv, y);
    ln_k<<<MROWS, blk>>>(y, g1, be1, x);

    // FFN
    mma_gemm<EPI_RELU><<<dim3(FFv / 128, MROWS / 128), blk, GSMEM_BYTES>>>(
        x, W1, b1, nullptr, nullptr, Dv, FFv, hh);
    mma_gemm<EPI_RES><<<dim3(Dv / 128, MROWS / 128), blk, GSMEM_BYTES>>>(
        hh, W2, b2, x, nullptr, FFv, Dv, y);
    ln_k<<<MROWS, blk>>>(y, g2, be2, outp);
}

// round 5
// speedup vs baseline: 3.9326x; 3.3888x over previous
#include <cuda_runtime.h>
#include <cstdint>

#define LQv 2048
#define BZv 8
#define Dv 1024
#define NHv 16
#define NKv 4
#define FFv 2048
#define HDv 64
#define MROWS (LQv * BZv)   // 16384

// ================= scratch (single blob, no allocations) =================
#define MDsz ((size_t)MROWS * Dv)
#define OFF_Q     ((size_t)0)
#define OFF_VAL   (OFF_Q   + MDsz)
#define OFF_OFFA  (OFF_VAL + MDsz)                       // [MROWS,128]
#define OFF_AO    (OFF_OFFA + (size_t)MROWS * 128)
#define OFF_X     (OFF_AO  + MDsz)
#define OFF_Y     (OFF_X   + MDsz)
#define OFF_H     (OFF_Y   + MDsz)                       // [MROWS,FF]
#define OFF_WOFA  (OFF_H   + (size_t)MROWS * FFv)        // [1024,128] row-major
#define OFF_BOFA  (OFF_WOFA + (size_t)Dv * 128)          // [128]
#define SCRATCH_FLOATS (OFF_BOFA + 128)

__device__ float g_scratch[SCRATCH_FLOATS];

__device__ __forceinline__ uint32_t smem_u32(const void* p) {
    uint32_t a;
    asm("{ .reg .u64 t; cvta.to.shared.u64 t, %1; cvt.u32.u64 %0, t; }"
        : "=r"(a) : "l"(p));
    return a;
}

#define CP16(dst, src) \
    asm volatile("cp.async.cg.shared.global [%0], [%1], 16;" \
                 :: "r"(dst), "l"(src))
#define CP_COMMIT() asm volatile("cp.async.commit_group;")
#define CP_WAIT1()  asm volatile("cp.async.wait_group 1;")
#define CP_WAIT0()  asm volatile("cp.async.wait_group 0;")

// ================= prep: fuse Woff|Wa -> Wofa[K=1024][N=128] =================
__global__ __launch_bounds__(256)
void prep_offa_k(const float* __restrict__ Woff, const float* __restrict__ boff,
                 const float* __restrict__ Wa,   const float* __restrict__ ba,
                 float* __restrict__ Wofa, float* __restrict__ bout)
{
    int idx = blockIdx.x * 256 + threadIdx.x;   // 1024*128
    int k = idx >> 7, n = idx & 127;
    float v = (n < 64) ? Woff[(size_t)k * 64 + n] : Wa[(size_t)k * 64 + (n - 64)];
    Wofa[idx] = v;
    if (idx < 128) bout[idx] = (idx < 64) ? boff[idx] : ba[idx - 64];
}

// ================= elementwise add =================
__global__ __launch_bounds__(256)
void add_k(const float* __restrict__ a, const float* __restrict__ b,
           float* __restrict__ o)
{
    size_t i = ((size_t)blockIdx.x * 256 + threadIdx.x) * 4;
    float4 va = *reinterpret_cast<const float4*>(a + i);
    float4 vb = *reinterpret_cast<const float4*>(b + i);
    float4 vo;
    vo.x = va.x + vb.x; vo.y = va.y + vb.y;
    vo.z = va.z + vb.z; vo.w = va.w + vb.w;
    *reinterpret_cast<float4*>(o + i) = vo;
}

// ================= tf32 mma.sync GEMM, cp.async pipeline =================
// C[M,N] = A[M,K] @ B[K,N] + bias (+epi). BM=BN=128, BK=32, 256 thr, 8 warps.
// SMEM: A [128][36] (pad 4), B [32][136] (pad 8). 3 stages.
enum { EPI_BIAS = 0, EPI_MASK = 1, EPI_RELU = 2, EPI_RES = 3 };

#define SA 36
#define SB 136
#define A_F (128 * SA)            // 4608 floats
#define B_F (32 * SB)             // 4352 floats
#define STG_F (A_F + B_F)         // 8960 floats
#define NSTAGE 3
#define GSMEM_BYTES (NSTAGE * STG_F * 4)   // 107520 B

__device__ __forceinline__ void mma_tf32(float* c, const uint32_t* a,
                                         const uint32_t* b)
{
    asm volatile(
        "mma.sync.aligned.m16n8k8.row.col.f32.tf32.tf32.f32 "
        "{%0,%1,%2,%3}, {%4,%5,%6,%7}, {%8,%9}, {%0,%1,%2,%3};"
        : "+f"(c[0]), "+f"(c[1]), "+f"(c[2]), "+f"(c[3])
        : "r"(a[0]), "r"(a[1]), "r"(a[2]), "r"(a[3]),
          "r"(b[0]), "r"(b[1]));
}

template <int EPI>
__global__ __launch_bounds__(256, 2)
void mma_gemm(const float* __restrict__ A, const float* __restrict__ B,
              const float* __restrict__ bias, const float* __restrict__ res,
              const unsigned char* __restrict__ mask,
              int K, int N, float* __restrict__ C)
{
    extern __shared__ float sm[];
    const uint32_t sb0 = smem_u32(sm);

    const int tid = threadIdx.x;
    const int lane = tid & 31;
    const int wid = tid >> 5;
    const int warp_m = wid & 1;        // 2 warps in M (64 rows each)
    const int warp_n = wid >> 1;       // 4 warps in N (32 cols each)
    const int g = lane >> 2, t = lane & 3;
    const int row0 = blockIdx.y * 128;
    const int col0 = blockIdx.x * 128;

    // per-thread cp.async geometry (4 A-chunks, 4 B-chunks of 16B each)
    int am[4], akc[4], bk[4], bnc[4];
#pragma unroll
    for (int it = 0; it < 4; it++) {
        int id = tid + it * 256;
        am[it] = id >> 3;  akc[it] = id & 7;     // A: m 0..127, kchunk 0..7
        bk[it] = id >> 5;  bnc[it] = id & 31;    // B: k 0..31, nchunk 0..31
    }

#define ISSUE(c_, s_)                                                        \
    {                                                                        \
        const float* Ap_ = A + (size_t)row0 * K + ((c_) << 5);               \
        const float* Bp_ = B + (size_t)((c_) << 5) * N + col0;               \
        uint32_t ab_ = sb0 + (uint32_t)(s_) * (STG_F * 4);                   \
        uint32_t bb_ = ab_ + A_F * 4;                                        \
        _Pragma("unroll")                                                    \
        for (int it = 0; it < 4; it++)                                       \
            CP16(ab_ + (uint32_t)(am[it] * SA + akc[it] * 4) * 4,            \
                 Ap_ + (size_t)am[it] * K + akc[it] * 4);                    \
        _Pragma("unroll")                                                    \
        for (int it = 0; it < 4; it++)                                       \
            CP16(bb_ + (uint32_t)(bk[it] * SB + bnc[it] * 4) * 4,            \
                 Bp_ + (size_t)bk[it] * N + bnc[it] * 4);                    \
        CP_COMMIT();                                                         \
    }

    float acc[4][4][4];
#pragma unroll
    for (int mi = 0; mi < 4; mi++)
#pragma unroll
        for (int ni = 0; ni < 4; ni++)
#pragma unroll
            for (int j = 0; j < 4; j++) acc[mi][ni][j] = 0.f;

    const int NC = K >> 5;
    ISSUE(0, 0);
    ISSUE(1, 1);

    for (int c = 0; c < NC; c++) {
        const int s = c % NSTAGE;
        if (c + 2 < NC) { CP_WAIT1(); } else { CP_WAIT0(); }
        __syncthreads();
        if (c + 2 < NC) ISSUE(c + 2, (c + 2) % NSTAGE);

        const float* as = sm + s * STG_F;
        const float* bs = as + A_F;
#pragma unroll
        for (int kk = 0; kk < 4; kk++) {
            uint32_t af[4][4], bf[4][2];
#pragma unroll
            for (int mi = 0; mi < 4; mi++) {
                int base = (warp_m * 64 + mi * 16 + g) * SA + kk * 8 + t;
                af[mi][0] = __float_as_uint(as[base]);
                af[mi][1] = __float_as_uint(as[base + 8 * SA]);
                af[mi][2] = __float_as_uint(as[base + 4]);
                af[mi][3] = __float_as_uint(as[base + 8 * SA + 4]);
            }
#pragma unroll
            for (int ni = 0; ni < 4; ni++) {
                int bb = (kk * 8 + t) * SB + warp_n * 32 + ni * 8 + g;
                bf[ni][0] = __float_as_uint(bs[bb]);
                bf[ni][1] = __float_as_uint(bs[bb + 4 * SB]);
            }
#pragma unroll
            for (int mi = 0; mi < 4; mi++)
#pragma unroll
                for (int ni = 0; ni < 4; ni++)
                    mma_tf32(acc[mi][ni], af[mi], bf[ni]);
        }
    }
#undef ISSUE

    // ---- epilogue ----
#pragma unroll
    for (int mi = 0; mi < 4; mi++) {
        int rA = row0 + warp_m * 64 + mi * 16 + g;     // rows rA, rA+8
#pragma unroll
        for (int half = 0; half < 2; half++) {
            int r = rA + half * 8;
            unsigned char mrow = 0;
            if (EPI == EPI_MASK) {
                int b = r & (BZv - 1);
                int qq = r >> 3;
                mrow = mask[b * LQv + qq];
            }
#pragma unroll
            for (int ni = 0; ni < 4; ni++) {
                int cc = col0 + warp_n * 32 + ni * 8 + t * 2;
                float v0 = acc[mi][ni][half * 2 + 0] + bias[cc + 0];
                float v1 = acc[mi][ni][half * 2 + 1] + bias[cc + 1];
                if (EPI == EPI_MASK && mrow) { v0 = 0.f; v1 = 0.f; }
                if (EPI == EPI_RELU) { v0 = fmaxf(v0, 0.f); v1 = fmaxf(v1, 0.f); }
                if (EPI == EPI_RES) {
                    float2 rv = *reinterpret_cast<const float2*>(
                        &res[(size_t)r * N + cc]);
                    v0 += rv.x; v1 += rv.y;
                }
                *reinterpret_cast<float2*>(&C[(size_t)r * N + cc]) =
                    make_float2(v0, v1);
            }
        }
    }
}

// ================= softmax + grid_sample1d + head combine =================
__global__ __launch_bounds__(256)
void sample_k(const float* __restrict__ value,   // [Lv, BZ, D]
              const float* __restrict__ offa,    // [MROWS, 128]
              const float* __restrict__ refp,    // [BZ, LQ]
              const float* __restrict__ snip,    // [BZ]
              float* __restrict__ out)           // [MROWS, D]
{
    int t = blockIdx.x * 256 + threadIdx.x;
    int c = t & 63;
    int gidx = t >> 6;
    int h = gidx & (NHv - 1);
    int rb = gidx >> 4;
    int b = rb & (BZv - 1);
    int q = rb >> 3;

    const float* ol = offa + (size_t)rb * 128 + h * NKv;
    const float* al = ol + 64;

    float a0 = al[0], a1 = al[1], a2 = al[2], a3 = al[3];
    float m = fmaxf(fmaxf(a0, a1), fmaxf(a2, a3));
    float e0 = __expf(a0 - m), e1 = __expf(a1 - m);
    float e2 = __expf(a2 - m), e3 = __expf(a3 - m);
    float inv_s = 1.f / (e0 + e1 + e2 + e3);
    float ak[4] = {e0 * inv_s, e1 * inv_s, e2 * inv_s, e3 * inv_s};

    float refv = refp[b * LQv + q];
    float inv_sn = 1.f / snip[b];

    float acc = 0.f;
#pragma unroll
    for (int k = 0; k < NKv; k++) {
        float loc = refv + ol[k] * inv_sn;
        float x = loc * (float)(LQv - 1);
        float x0f = floorf(x);
        float w1 = x - x0f;
        float w0 = 1.f - w1;
        float x0c = fminf(fmaxf(x0f, -2.f), (float)(LQv + 1));
        int i0 = (int)x0c;
        int i1 = i0 + 1;
        float v0 = 0.f, v1 = 0.f;
        if (x0f >= 0.f && x0f <= (float)(LQv - 1))
            v0 = value[((size_t)i0 * BZv + b) * Dv + h * HDv + c];
        if (x0f >= -1.f && x0f <= (float)(LQv - 2))
            v1 = value[((size_t)i1 * BZv + b) * Dv + h * HDv + c];
        acc += ak[k] * (w0 * v0 + w1 * v1);
    }
    out[(size_t)rb * Dv + h * HDv + c] = acc;
}

// ================= LayerNorm D=1024 =================
__global__ __launch_bounds__(256)
void ln_k(const float* __restrict__ in, const float* __restrict__ gam,
          const float* __restrict__ bet, float* __restrict__ out)
{
    int row = blockIdx.x;
    const float* xp = in + (size_t)row * Dv;
    int c4 = threadIdx.x * 4;
    float4 v = *reinterpret_cast<const float4*>(&xp[c4]);
    float s  = v.x + v.y + v.z + v.w;
    float ss = v.x * v.x + v.y * v.y + v.z * v.z + v.w * v.w;
#pragma unroll
    for (int o = 16; o > 0; o >>= 1) {
        s  += __shfl_xor_sync(0xffffffffu, s, o);
        ss += __shfl_xor_sync(0xffffffffu, ss, o);
    }
    __shared__ float sh_s[8], sh_ss[8];
    int w = threadIdx.x >> 5;
    if ((threadIdx.x & 31) == 0) { sh_s[w] = s; sh_ss[w] = ss; }
    __syncthreads();
    s = 0.f; ss = 0.f;
#pragma unroll
    for (int i = 0; i < 8; i++) { s += sh_s[i]; ss += sh_ss[i]; }
    float mean = s * (1.f / Dv);
    float var  = ss * (1.f / Dv) - mean * mean;
    float inv  = rsqrtf(var + 1e-5f);
    float4 gv = *reinterpret_cast<const float4*>(&gam[c4]);
    float4 bvv = *reinterpret_cast<const float4*>(&bet[c4]);
    float4 o;
    o.x = (v.x - mean) * inv * gv.x + bvv.x;
    o.y = (v.y - mean) * inv * gv.y + bvv.y;
    o.z = (v.z - mean) * inv * gv.z + bvv.z;
    o.w = (v.w - mean) * inv * gv.w + bvv.w;
    *reinterpret_cast<float4*>(&out[(size_t)row * Dv + c4]) = o;
}

// ================= launch =================
extern "C" void kernel_launch(void* const* d_in, const int* in_sizes, int n_in,
                              void* d_out, int out_size)
{
    const float* src  = (const float*)d_in[0];
    const float* pos  = (const float*)d_in[1];
    const unsigned char* mask = (const unsigned char*)d_in[2];
    const float* refp = (const float*)d_in[3];
    const float* snip = (const float*)d_in[4];
    const float* Wv   = (const float*)d_in[5];
    const float* bv   = (const float*)d_in[6];
    const float* Woff = (const float*)d_in[7];
    const float* boff = (const float*)d_in[8];
    const float* Wa   = (const float*)d_in[9];
    const float* ba   = (const float*)d_in[10];
    const float* Wo   = (const float*)d_in[11];
    const float* bo   = (const float*)d_in[12];
    const float* W1   = (const float*)d_in[13];
    const float* b1   = (const float*)d_in[14];
    const float* W2   = (const float*)d_in[15];
    const float* b2   = (const float*)d_in[16];
    const float* g1   = (const float*)d_in[17];
    const float* be1  = (const float*)d_in[18];
    const float* g2   = (const float*)d_in[19];
    const float* be2  = (const float*)d_in[20];
    float* outp = (float*)d_out;

    float* scratch = nullptr;
    cudaGetSymbolAddress((void**)&scratch, g_scratch);
    float* q    = scratch + OFF_Q;
    float* val  = scratch + OFF_VAL;
    float* offa = scratch + OFF_OFFA;
    float* ao   = scratch + OFF_AO;
    float* x    = scratch + OFF_X;
    float* y    = scratch + OFF_Y;
    float* hh   = scratch + OFF_H;
    float* wofa = scratch + OFF_WOFA;
    float* bofa = scratch + OFF_BOFA;

    cudaFuncSetAttribute(mma_gemm<EPI_MASK>,
        cudaFuncAttributeMaxDynamicSharedMemorySize, GSMEM_BYTES);
    cudaFuncSetAttribute(mma_gemm<EPI_BIAS>,
        cudaFuncAttributeMaxDynamicSharedMemorySize, GSMEM_BYTES);
    cudaFuncSetAttribute(mma_gemm<EPI_RELU>,
        cudaFuncAttributeMaxDynamicSharedMemorySize, GSMEM_BYTES);
    cudaFuncSetAttribute(mma_gemm<EPI_RES>,
        cudaFuncAttributeMaxDynamicSharedMemorySize, GSMEM_BYTES);

    const dim3 blk(256);

    // prep (tiny)
    prep_offa_k<<<(Dv * 128) / 256, blk>>>(Woff, boff, Wa, ba, wofa, bofa);

    // q = src + pos
    add_k<<<(size_t)MROWS * Dv / 4 / 256, blk>>>(src, pos, q);

    // value = src @ Wv + bv (masked)
    mma_gemm<EPI_MASK><<<dim3(Dv / 128, MROWS / 128), blk, GSMEM_BYTES>>>(
        src, Wv, bv, nullptr, mask, Dv, Dv, val);

    // offsets + attn logits fused: [MROWS,128]
    mma_gemm<EPI_BIAS><<<dim3(1, MROWS / 128), blk, GSMEM_BYTES>>>(
        q, wofa, bofa, nullptr, nullptr, Dv, 128, offa);

    // softmax + grid-sample + combine
    sample_k<<<(size_t)MROWS * NHv * HDv / 256, blk>>>(val, offa, refp, snip, ao);

    // out proj + residual, LN1
    mma_gemm<EPI_RES><<<dim3(Dv / 128, MROWS / 128), blk, GSMEM_BYTES>>>(
        ao, Wo, bo, src, nullptr, Dv, Dv, y);
    ln_k<<<MROWS, blk>>>(y, g1, be1, x);

    // FFN
    mma_gemm<EPI_RELU><<<dim3(FFv / 128, MROWS / 128), blk, GSMEM_BYTES>>>(
        x, W1, b1, nullptr, nullptr, Dv, FFv, hh);
    mma_gemm<EPI_RES><<<dim3(Dv / 128, MROWS / 128), blk, GSMEM_BYTES>>>(
        hh, W2, b2, x, nullptr, FFv, Dv, y);
    ln_k<<<MROWS, blk>>>(y, g2, be2, outp);
}